// round 12
// baseline (speedup 1.0000x reference)
#include <cuda_runtime.h>
#include <math.h>

// Problem constants
#define BB   1024
#define NN   100
#define HH   128
#define STEPS 128
#define NEGV -1000000000.0f
#define NPAD 132

// packed f32x2 helpers (Blackwell FFMA2 — per-lane IEEE fma on packed pairs)
#define PK2(d, x, y)  asm("mov.b64 %0, {%1, %2};" : "=l"(d) : "f"(x), "f"(y))
#define UPK2(x, y, d) asm("mov.b64 {%0, %1}, %2;" : "=f"(x), "=f"(y) : "l"(d))
#define FMA2(d, a, b) asm("fma.rn.f32x2 %0, %1, %2, %0;" : "+l"(d) : "l"(a), "l"(b))

// -------- device scratch ----
__device__ float g_K [BB*NN*HH];
__device__ float g_V [BB*NN*HH];
__device__ float g_K2[BB*NN*HH];
__device__ float g_Qe[BB*NN*HH];
__device__ float g_qpool[BB*HH];
__device__ float g_Wqf[HH*(HH+1)];
__device__ float g_WfoldT[HH*HH];
__device__ float g_Wpq[HH*HH];
__device__ float g_M [(size_t)BB*NN*8*NN];  // [b][i][h][n]  (C3 folded in)
__device__ float g_C2[BB*8*NN];             // [b][h][n]

// ======================= fold kernel =================================
__global__ void fold_kernel(const float* __restrict__ fc_w,
                            const float* __restrict__ fc1_w,
                            const float* __restrict__ Wq,
                            const float* __restrict__ Wo,
                            const float* __restrict__ Wk2)
{
    int mat = blockIdx.y;
    int r   = blockIdx.x;
    int j   = threadIdx.x;
    if (mat == 0) {
        if (j < 129) {
            float acc = 0.f;
            #pragma unroll 8
            for (int i = 0; i < 128; i++) acc += Wq[r*128 + i] * fc_w[i*129 + j];
            g_Wqf[r*129 + j] = 0.25f * acc;
        }
    } else if (mat == 1) {
        if (j < 128) {
            float acc = 0.f;
            #pragma unroll 8
            for (int i = 0; i < 128; i++) acc += Wk2[i*128 + j] * Wo[i*128 + r];
            g_WfoldT[r*128 + j] = (1.0f / sqrtf(128.0f)) * acc;
        }
    } else {
        if (j < 128) {
            float acc = 0.f;
            #pragma unroll 8
            for (int i = 0; i < 128; i++) acc += Wq[r*128 + i] * fc1_w[i*128 + j];
            g_Wpq[r*128 + j] = 0.25f * acc;
        }
    }
}

// ======================= GEMM: out = A @ W^T (FFMA2, A transposed in smem) ==
#define GM_TILE 64
#define ATPAD 68
#define GEMM_SMEM ((128*132 + 128*ATPAD) * 4)

__global__ __launch_bounds__(256) void gemm_kernel(const float* __restrict__ enc,
                                                   const float* __restrict__ pool,
                                                   const float* __restrict__ Wk,
                                                   const float* __restrict__ Wv)
{
    extern __shared__ float sm[];
    float* sW  = sm;                 // [128][132]  sW[k*132 + c] = W[c][k]
    float* sAT = sm + 128*132;       // [128][68]   sAT[k*68 + r] = A[row0+r][k]

    int slice = blockIdx.y;
    const float* A; const float* W; float* O; int rows; int ldw = 128;
    if      (slice == 0) { A = enc;  W = Wk;       O = g_K;     rows = BB*NN; }
    else if (slice == 1) { A = enc;  W = Wv;       O = g_V;     rows = BB*NN; }
    else if (slice == 2) { A = enc;  W = g_WfoldT; O = g_K2;    rows = BB*NN; }
    else if (slice == 3) { A = enc;  W = g_Wqf;    O = g_Qe;    rows = BB*NN; ldw = 129; }
    else                 { A = pool; W = g_Wpq;    O = g_qpool; rows = BB;    }

    int row0 = blockIdx.x * GM_TILE;
    if (row0 >= rows) return;
    int tid = threadIdx.x;

    for (int i = tid; i < 128*128; i += 256) {
        int c = i >> 7, m = i & 127;
        sW[m*132 + c] = W[c*ldw + m];
    }
    for (int i = tid; i < GM_TILE*128; i += 256) {
        int r = i >> 7, k = i & 127;
        sAT[k*ATPAD + r] = A[(row0 + r)*128 + k];
    }
    __syncthreads();

    int warp = tid >> 5, lane = tid & 31;
    int r0 = warp * 8, c0 = lane * 4;

    unsigned long long accp[4][4];
    #pragma unroll
    for (int c = 0; c < 4; c++)
        #pragma unroll
        for (int t = 0; t < 4; t++) PK2(accp[c][t], 0.f, 0.f);

    #pragma unroll 4
    for (int k = 0; k < 128; k++) {
        float4 w4 = *(const float4*)&sW[k*132 + c0];
        unsigned long long wd[4];
        PK2(wd[0], w4.x, w4.x); PK2(wd[1], w4.y, w4.y);
        PK2(wd[2], w4.z, w4.z); PK2(wd[3], w4.w, w4.w);
        float4 a04 = *(const float4*)&sAT[k*ATPAD + r0];
        float4 a14 = *(const float4*)&sAT[k*ATPAD + r0 + 4];
        unsigned long long ap[4];
        PK2(ap[0], a04.x, a04.y);
        PK2(ap[1], a04.z, a04.w);
        PK2(ap[2], a14.x, a14.y);
        PK2(ap[3], a14.z, a14.w);
        #pragma unroll
        for (int c = 0; c < 4; c++)
            #pragma unroll
            for (int t = 0; t < 4; t++) FMA2(accp[c][t], ap[t], wd[c]);
    }

    #pragma unroll
    for (int t = 0; t < 4; t++) {
        float4 v0, v1;
        UPK2(v0.x, v1.x, accp[0][t]);
        UPK2(v0.y, v1.y, accp[1][t]);
        UPK2(v0.z, v1.z, accp[2][t]);
        UPK2(v0.w, v1.w, accp[3][t]);
        *(float4*)&O[(size_t)(row0 + r0 + 2*t    )*128 + c0] = v0;
        *(float4*)&O[(size_t)(row0 + r0 + 2*t + 1)*128 + c0] = v1;
    }
}

// ======================= score precompute ===================================
#define SP_SMEM (NN*128*4)
__global__ __launch_bounds__(256, 2) void score_pre_kernel()
{
    extern __shared__ float sQe[];
    int b = blockIdx.x, tid = threadIdx.x;
    int h = tid >> 5, lane = tid & 31;

    const float* qe = g_Qe + (size_t)b*NN*HH;
    for (int j = tid; j < NN*HH/4; j += 256)
        *(float4*)&sQe[j*4] = ((const float4*)qe)[j];

    float kr[4][16];
    float wc[16], qp[16];
    #pragma unroll
    for (int j = 0; j < 16; j++) {
        wc[j] = g_Wqf[(h*16+j)*129 + 128];
        qp[j] = g_qpool[b*HH + h*16 + j];
    }
    #pragma unroll
    for (int k = 0; k < 4; k++) {
        int n = lane + 32*k;
        if (n < NN) {
            const float* kp = g_K + (size_t)b*NN*HH + (size_t)n*HH + h*16;
            #pragma unroll
            for (int j = 0; j < 16; j += 4) {
                float4 v = *(const float4*)&kp[j];
                kr[k][j]=v.x; kr[k][j+1]=v.y; kr[k][j+2]=v.z; kr[k][j+3]=v.w;
            }
        }
    }
    float a3s[4];
    #pragma unroll
    for (int k = 0; k < 4; k++) {
        int n = lane + 32*k;
        a3s[k] = 0.f;
        if (n < NN) {
            float a2 = 0.f, a3 = 0.f;
            #pragma unroll
            for (int j = 0; j < 16; j++) { a2 += kr[k][j]*wc[j]; a3 += kr[k][j]*qp[j]; }
            g_C2[((size_t)b*8 + h)*NN + n] = a2;
            a3s[k] = a3;
        }
    }
    __syncthreads();

    float* Mb = g_M + (size_t)b*NN*8*NN;
    for (int i = 0; i < NN; i++) {
        float q[16];
        #pragma unroll
        for (int j = 0; j < 16; j += 4) {
            float4 v = *(const float4*)&sQe[i*128 + h*16 + j];
            q[j]=v.x; q[j+1]=v.y; q[j+2]=v.z; q[j+3]=v.w;
        }
        #pragma unroll
        for (int k = 0; k < 4; k++) {
            int n = lane + 32*k;
            if (n < NN) {
                float acc = 0.f;
                #pragma unroll
                for (int j = 0; j < 16; j++) acc += kr[k][j]*q[j];
                Mb[((size_t)i*8 + h)*NN + n] = acc + a3s[k];
            }
        }
    }
}

// ======================= decode kernel ======================================
// r11 structure; C and D dots use packed f32x2 FFMA2 with smem pairs loaded
// directly as longlong2 (no packing movs). smem ~59 KB -> 3 CTAs/SM.
#define DEC_SMEM_FLOATS (NN*NPAD + 832 + 8 + 256 + 128 + 128 + 104 + 104)
#define DEC_SMEM (DEC_SMEM_FLOATS * 4)

__global__ __launch_bounds__(256, 3) void decode_kernel(const float* __restrict__ capacity,
                                                        const float* __restrict__ demand,
                                                        float* __restrict__ out)
{
    extern __shared__ float sm[];
    float* sK2   = sm;                    // [100][132]
    float* sAttn = sK2   + NN*NPAD;       // [8][104] halves at +0/+52 (unnormalized e)
    float* sRden = sAttn + 832;           // 8
    float* sPartA= sRden + 8;             // 256
    float* sG    = sPartA+ 256;           // 128
    float* sU    = sG    + 128;           // 128 (pads 100..127 = -inf, never rewritten)
    float* sMask = sU    + 128;           // 104
    float* sDem  = sMask + 104;           // 104

    __shared__ float sCap;
    __shared__ int   sIdx;
    __shared__ int   sDone;

    int b = blockIdx.x, tid = threadIdx.x;
    int warp = tid >> 5, lane = tid & 31;
    int d = tid & 127, half = tid >> 7, hh = d >> 4;

    // ---- loads ----
    {
        const float4* gK2 = (const float4*)(g_K2 + (size_t)b*NN*HH);
        for (int j = tid; j < NN*HH/4; j += 256) {
            int n = j >> 5; int c = (j & 31) << 2;
            *(float4*)&sK2[n*NPAD + c] = gK2[j];
        }
    }
    // V pre-packed into f32x2 pairs over n: vpk[i] = (V[2i,d], V[2i+1,d])
    unsigned long long vpk[25];
    {
        const float* vg = g_V + (size_t)b*NN*HH + (size_t)(half*50)*HH + d;
        #pragma unroll
        for (int i = 0; i < 25; i++) {
            float v0 = vg[(2*i)*HH];
            float v1 = vg[(2*i+1)*HH];
            PK2(vpk[i], v0, v1);
        }
    }
    if (tid < 100) sDem[tid] = demand[b*NN + tid];
    if (tid >= 100 && tid < 128) sU[tid] = -INFINITY;   // argmax pads (never rewritten)
    if (tid == 0) { sCap = capacity[b]; sIdx = 0; sDone = 0; }

    float c2reg[4];
    #pragma unroll
    for (int k = 0; k < 4; k++) {
        int n = lane + 32*k;
        c2reg[k] = (n < 100) ? g_C2[(size_t)b*800 + warp*100 + n] : 0.f;
    }
    float mrow[4];
    {
        const float* mp = g_M + ((size_t)b*NN*8 + warp)*NN;
        #pragma unroll
        for (int k = 0; k < 4; k++) { int n = lane + 32*k; mrow[k] = (n < NN) ? mp[n] : 0.f; }
    }
    __syncthreads();

    const float base_cap = capacity[0];

    // ---- initial mask (index=0, mask1=0, go_depot=1) ----
    if (warp == 0) {
        float cap0 = sCap; int cnt = 0;
        #pragma unroll
        for (int k = 0; k < 4; k++) {
            int n = lane + 32*k;
            if (n >= 1 && n < 100) {
                float m = (sDem[n] > cap0) ? 1.f : 0.f;
                sMask[n] = m;
                if (m == 0.f) cnt++;
            }
        }
        #pragma unroll
        for (int o = 16; o; o >>= 1) cnt += __shfl_xor_sync(0xffffffffu, cnt, o);
        if (lane == 0) sMask[0] = (cnt == 0) ? 0.f : 1.f;
    }
    __syncthreads();

    float logTot = 0.f;
    int   vis    = 0;
    unsigned m1bits = 0;   // warp0: mask1 bits for n = lane + 32k
    int sStop = STEPS;

    for (int s = 0; s < STEPS; s++) {
        // ---- B: e = exp(score) unnormalized; per-head 1/sum ----
        {
            float cap = sCap;
            float e[4]; float sum = 0.f;
            #pragma unroll
            for (int k = 0; k < 4; k++) {
                int n = lane + 32*k;
                float ee = 0.f;
                if (n < 100) {
                    float v = (sMask[n] > 0.f) ? NEGV : fmaf(cap, c2reg[k], mrow[k]);
                    ee = __expf(v);
                }
                e[k] = ee; sum += ee;
            }
            #pragma unroll
            for (int o = 16; o; o >>= 1) sum += __shfl_xor_sync(0xffffffffu, sum, o);
            #pragma unroll
            for (int k = 0; k < 4; k++) {
                int n = lane + 32*k;
                if (n < 100) sAttn[warp*104 + n + ((n >= 50) ? 2 : 0)] = e[k];
            }
            if (lane == 0) sRden[warp] = 1.0f / sum;
        }
        __syncthreads();

        // ---- C: glimpse partials — packed f32x2 (V pre-packed) ----
        {
            const float* an = sAttn + hh*104 + half*52;   // 16B-aligned
            unsigned long long ca0, ca1;
            PK2(ca0, 0.f, 0.f); PK2(ca1, 0.f, 0.f);
            #pragma unroll
            for (int i = 0; i < 48; i += 4) {
                longlong2 a2 = *(const longlong2*)&an[i]; // pairs (i,i+1),(i+2,i+3)
                FMA2(ca0, a2.x, vpk[i >> 1]);
                FMA2(ca1, a2.y, vpk[(i >> 1) + 1]);
            }
            {   // tail n = 48,49
                unsigned long long at = *(const unsigned long long*)&an[48];
                FMA2(ca0, at, vpk[24]);
            }
            float p0, p1, p2, p3;
            UPK2(p0, p1, ca0);
            UPK2(p2, p3, ca1);
            sPartA[tid] = (p0 + p2) + (p1 + p3);
        }
        __syncthreads();

        float uv[4]; float vmax = -INFINITY; int imax = 0;

        // ---- warps 0-3: g-combine (deferred 1/sum), u (packed D), argmax ----
        if (tid < 128) {
            sG[tid] = (sPartA[tid] + sPartA[tid + 128]) * sRden[hh];
            asm volatile("bar.sync 1, 128;" ::: "memory");

            if (tid < 100) {
                const float* kp = sK2 + tid*NPAD;   // 16B-aligned (132*4=528=33*16)
                unsigned long long b0, b1, b2, b3;
                PK2(b0, 0.f, 0.f); PK2(b1, 0.f, 0.f);
                PK2(b2, 0.f, 0.f); PK2(b3, 0.f, 0.f);
                #pragma unroll
                for (int j = 0; j < 128; j += 8) {
                    longlong2 kd0 = *(const longlong2*)&kp[j];
                    longlong2 gd0 = *(const longlong2*)&sG[j];
                    FMA2(b0, kd0.x, gd0.x);
                    FMA2(b1, kd0.y, gd0.y);
                    longlong2 kd1 = *(const longlong2*)&kp[j + 4];
                    longlong2 gd1 = *(const longlong2*)&sG[j + 4];
                    FMA2(b2, kd1.x, gd1.x);
                    FMA2(b3, kd1.y, gd1.y);
                }
                float e0, e1, e2, e3, e4, e5, e6, e7;
                UPK2(e0, e1, b0); UPK2(e2, e3, b1);
                UPK2(e4, e5, b2); UPK2(e6, e7, b3);
                float t = ((e0 + e1) + (e2 + e3)) + ((e4 + e5) + (e6 + e7));
                sU[tid] = (sMask[tid] > 0.f) ? NEGV : 10.0f * tanhf(t);
            }
            asm volatile("bar.sync 1, 128;" ::: "memory");

            // warp0: argmax + publish sIdx ASAP (sU pads 100..127 are -inf)
            if (warp == 0) {
                #pragma unroll
                for (int k = 0; k < 4; k++) uv[k] = sU[lane + 32*k];
                #pragma unroll
                for (int k = 0; k < 4; k++) {
                    int n = lane + 32*k;
                    if (uv[k] > vmax) { vmax = uv[k]; imax = n; }
                }
                #pragma unroll
                for (int o = 16; o; o >>= 1) {
                    float ov = __shfl_down_sync(0xffffffffu, vmax, o);
                    int   oi = __shfl_down_sync(0xffffffffu, imax, o);
                    if (ov > vmax || (ov == vmax && oi < imax)) { vmax = ov; imax = oi; }
                }
                vmax = __shfl_sync(0xffffffffu, vmax, 0);
                imax = __shfl_sync(0xffffffffu, imax, 0);
                if (lane == 0) sIdx = imax;
            }
        }
        __syncthreads();   // publish sIdx

        // ---- ALL warps: prefetch next M row early (hides DRAM under tail) ----
        {
            int idx = sIdx;
            const float* mp = g_M + (((size_t)b*NN + idx)*8 + warp)*NN;
            #pragma unroll
            for (int k = 0; k < 4; k++) { int n = lane + 32*k; if (n < NN) mrow[k] = mp[n]; }
        }

        // ---- warp0 tail: logp, state, mask (overlaps M prefetch latency) ----
        if (warp == 0) {
            float sum = 0.f;
            #pragma unroll
            for (int k = 0; k < 4; k++) {
                int n = lane + 32*k;
                if (n < 100) sum += __expf(uv[k] - vmax);
            }
            #pragma unroll
            for (int o = 16; o; o >>= 1) sum += __shfl_xor_sync(0xffffffffu, sum, o);

            float capNew = 0.f;
            if (lane == 0) {
                float logp = -logf(sum);
                if (vis < 99) logTot += logp;
                out[(size_t)b*STEPS + s] = (float)imax;
                float seld = sDem[imax];
                capNew = (imax == 0) ? base_cap : (sCap - seld);
                sCap = capNew;
            }
            capNew = __shfl_sync(0xffffffffu, capNew, 0);

            // mask1 (bits) + vis
            int kbit = imax >> 5;
            int owner = (lane == (imax & 31));
            unsigned newly = (owner && imax > 0 && !((m1bits >> kbit) & 1u)) ? 1u : 0u;
            unsigned bal = __ballot_sync(0xffffffffu, newly);
            if (bal) vis += 1;
            if (owner && imax > 0) m1bits |= (1u << kbit);

            int goDepot = (imax == 0);
            int cnt = 0;
            #pragma unroll
            for (int k = 0; k < 4; k++) {
                int n = lane + 32*k;
                if (n >= 1 && n < 100) {
                    float m1v = ((m1bits >> k) & 1u) ? 1.f : 0.f;
                    float m = fmaxf(m1v, (sDem[n] > capNew) ? 1.f : 0.f);
                    sMask[n] = m;
                    if (m == 0.f) cnt++;
                }
            }
            #pragma unroll
            for (int o = 16; o; o >>= 1) cnt += __shfl_xor_sync(0xffffffffu, cnt, o);
            if (lane == 0) {
                sMask[0] = (cnt == 0) ? 0.f : (goDepot ? 1.f : 0.f);
                sDone = (vis == 99 && imax == 0) ? 1 : 0;   // absorbing state
            }
        }
        __syncthreads();

        if (sDone) { sStop = s + 1; break; }
    }

    // zero-fill remaining actions (absorbing state always selects depot; logp gated)
    for (int j = sStop + tid; j < STEPS; j += 256) out[(size_t)b*STEPS + j] = 0.f;
    if (tid == 0) out[(size_t)BB*STEPS + b] = logTot;
}

// ======================= launcher ===========================================
extern "C" void kernel_launch(void* const* d_in, const int* in_sizes, int n_in,
                              void* d_out, int out_size)
{
    const float* enc      = (const float*)d_in[0];
    const float* pool     = (const float*)d_in[1];
    const float* capacity = (const float*)d_in[2];
    const float* demand   = (const float*)d_in[3];
    const float* fc_w     = (const float*)d_in[4];
    const float* fc1_w    = (const float*)d_in[5];
    const float* Wq       = (const float*)d_in[6];
    const float* Wk       = (const float*)d_in[7];
    const float* Wv       = (const float*)d_in[8];
    const float* Wo       = (const float*)d_in[9];
    const float* Wk2      = (const float*)d_in[10];
    float* out = (float*)d_out;

    cudaFuncSetAttribute(gemm_kernel,      cudaFuncAttributeMaxDynamicSharedMemorySize, GEMM_SMEM);
    cudaFuncSetAttribute(score_pre_kernel, cudaFuncAttributeMaxDynamicSharedMemorySize, SP_SMEM);
    cudaFuncSetAttribute(decode_kernel,    cudaFuncAttributeMaxDynamicSharedMemorySize, DEC_SMEM);

    fold_kernel<<<dim3(128, 3), 132>>>(fc_w, fc1_w, Wq, Wo, Wk2);
    gemm_kernel<<<dim3((BB*NN)/GM_TILE, 5), 256, GEMM_SMEM>>>(enc, pool, Wk, Wv);
    score_pre_kernel<<<BB, 256, SP_SMEM>>>();
    decode_kernel<<<BB, 256, DEC_SMEM>>>(capacity, demand, out);
}

// round 13
// speedup vs baseline: 1.0862x; 1.0862x over previous
#include <cuda_runtime.h>
#include <math.h>

// Problem constants
#define BB   1024
#define NN   100
#define HH   128
#define STEPS 128
#define NEGV -1000000000.0f
#define NPAD 132

// packed f32x2 helpers (Blackwell FFMA2 — bit-identical per-lane IEEE fma)
#define PK2(d, x, y)  asm("mov.b64 %0, {%1, %2};" : "=l"(d) : "f"(x), "f"(y))
#define UPK2(x, y, d) asm("mov.b64 {%0, %1}, %2;" : "=f"(x), "=f"(y) : "l"(d))
#define FMA2(d, a, b) asm("fma.rn.f32x2 %0, %1, %2, %0;" : "+l"(d) : "l"(a), "l"(b))

// -------- device scratch ----
__device__ float g_K [BB*NN*HH];
__device__ float g_V [BB*NN*HH];
__device__ float g_K2[BB*NN*HH];
__device__ float g_Qe[BB*NN*HH];
__device__ float g_qpool[BB*HH];
__device__ float g_Wqf[HH*(HH+1)];
__device__ float g_WfoldT[HH*HH];
__device__ float g_Wpq[HH*HH];
__device__ float g_M [(size_t)BB*NN*8*NN];  // [b][i][h][n]  (C3 folded in)
__device__ float g_C2[BB*8*NN];             // [b][h][n]

// ======================= fold kernel =================================
__global__ void fold_kernel(const float* __restrict__ fc_w,
                            const float* __restrict__ fc1_w,
                            const float* __restrict__ Wq,
                            const float* __restrict__ Wo,
                            const float* __restrict__ Wk2)
{
    int mat = blockIdx.y;
    int r   = blockIdx.x;
    int j   = threadIdx.x;
    if (mat == 0) {
        if (j < 129) {
            float acc = 0.f;
            #pragma unroll 8
            for (int i = 0; i < 128; i++) acc += Wq[r*128 + i] * fc_w[i*129 + j];
            g_Wqf[r*129 + j] = 0.25f * acc;
        }
    } else if (mat == 1) {
        if (j < 128) {
            float acc = 0.f;
            #pragma unroll 8
            for (int i = 0; i < 128; i++) acc += Wk2[i*128 + j] * Wo[i*128 + r];
            g_WfoldT[r*128 + j] = (1.0f / sqrtf(128.0f)) * acc;
        }
    } else {
        if (j < 128) {
            float acc = 0.f;
            #pragma unroll 8
            for (int i = 0; i < 128; i++) acc += Wq[r*128 + i] * fc1_w[i*128 + j];
            g_Wpq[r*128 + j] = 0.25f * acc;
        }
    }
}

// ======================= GEMM: out = A @ W^T (FFMA2, A transposed in smem) ==
#define GM_TILE 64
#define ATPAD 68
#define GEMM_SMEM ((128*132 + 128*ATPAD) * 4)

__global__ __launch_bounds__(256) void gemm_kernel(const float* __restrict__ enc,
                                                   const float* __restrict__ pool,
                                                   const float* __restrict__ Wk,
                                                   const float* __restrict__ Wv)
{
    extern __shared__ float sm[];
    float* sW  = sm;                 // [128][132]  sW[k*132 + c] = W[c][k]
    float* sAT = sm + 128*132;       // [128][68]   sAT[k*68 + r] = A[row0+r][k]

    int slice = blockIdx.y;
    const float* A; const float* W; float* O; int rows; int ldw = 128;
    if      (slice == 0) { A = enc;  W = Wk;       O = g_K;     rows = BB*NN; }
    else if (slice == 1) { A = enc;  W = Wv;       O = g_V;     rows = BB*NN; }
    else if (slice == 2) { A = enc;  W = g_WfoldT; O = g_K2;    rows = BB*NN; }
    else if (slice == 3) { A = enc;  W = g_Wqf;    O = g_Qe;    rows = BB*NN; ldw = 129; }
    else                 { A = pool; W = g_Wpq;    O = g_qpool; rows = BB;    }

    int row0 = blockIdx.x * GM_TILE;
    if (row0 >= rows) return;
    int tid = threadIdx.x;

    for (int i = tid; i < 128*128; i += 256) {
        int c = i >> 7, m = i & 127;
        sW[m*132 + c] = W[c*ldw + m];
    }
    for (int i = tid; i < GM_TILE*128; i += 256) {
        int r = i >> 7, k = i & 127;
        sAT[k*ATPAD + r] = A[(row0 + r)*128 + k];
    }
    __syncthreads();

    int warp = tid >> 5, lane = tid & 31;
    int r0 = warp * 8, c0 = lane * 4;

    unsigned long long accp[4][4];
    #pragma unroll
    for (int c = 0; c < 4; c++)
        #pragma unroll
        for (int t = 0; t < 4; t++) PK2(accp[c][t], 0.f, 0.f);

    #pragma unroll 4
    for (int k = 0; k < 128; k++) {
        float4 w4 = *(const float4*)&sW[k*132 + c0];
        unsigned long long wd[4];
        PK2(wd[0], w4.x, w4.x); PK2(wd[1], w4.y, w4.y);
        PK2(wd[2], w4.z, w4.z); PK2(wd[3], w4.w, w4.w);
        float4 a04 = *(const float4*)&sAT[k*ATPAD + r0];
        float4 a14 = *(const float4*)&sAT[k*ATPAD + r0 + 4];
        unsigned long long ap[4];
        PK2(ap[0], a04.x, a04.y);
        PK2(ap[1], a04.z, a04.w);
        PK2(ap[2], a14.x, a14.y);
        PK2(ap[3], a14.z, a14.w);
        #pragma unroll
        for (int c = 0; c < 4; c++)
            #pragma unroll
            for (int t = 0; t < 4; t++) FMA2(accp[c][t], ap[t], wd[c]);
    }

    #pragma unroll
    for (int t = 0; t < 4; t++) {
        float4 v0, v1;
        UPK2(v0.x, v1.x, accp[0][t]);
        UPK2(v0.y, v1.y, accp[1][t]);
        UPK2(v0.z, v1.z, accp[2][t]);
        UPK2(v0.w, v1.w, accp[3][t]);
        *(float4*)&O[(size_t)(row0 + r0 + 2*t    )*128 + c0] = v0;
        *(float4*)&O[(size_t)(row0 + r0 + 2*t + 1)*128 + c0] = v1;
    }
}

// ======================= score precompute ===================================
#define SP_SMEM (NN*128*4)
__global__ __launch_bounds__(256, 2) void score_pre_kernel()
{
    extern __shared__ float sQe[];
    int b = blockIdx.x, tid = threadIdx.x;
    int h = tid >> 5, lane = tid & 31;

    const float* qe = g_Qe + (size_t)b*NN*HH;
    for (int j = tid; j < NN*HH/4; j += 256)
        *(float4*)&sQe[j*4] = ((const float4*)qe)[j];

    float kr[4][16];
    float wc[16], qp[16];
    #pragma unroll
    for (int j = 0; j < 16; j++) {
        wc[j] = g_Wqf[(h*16+j)*129 + 128];
        qp[j] = g_qpool[b*HH + h*16 + j];
    }
    #pragma unroll
    for (int k = 0; k < 4; k++) {
        int n = lane + 32*k;
        if (n < NN) {
            const float* kp = g_K + (size_t)b*NN*HH + (size_t)n*HH + h*16;
            #pragma unroll
            for (int j = 0; j < 16; j += 4) {
                float4 v = *(const float4*)&kp[j];
                kr[k][j]=v.x; kr[k][j+1]=v.y; kr[k][j+2]=v.z; kr[k][j+3]=v.w;
            }
        }
    }
    float a3s[4];
    #pragma unroll
    for (int k = 0; k < 4; k++) {
        int n = lane + 32*k;
        a3s[k] = 0.f;
        if (n < NN) {
            float a2 = 0.f, a3 = 0.f;
            #pragma unroll
            for (int j = 0; j < 16; j++) { a2 += kr[k][j]*wc[j]; a3 += kr[k][j]*qp[j]; }
            g_C2[((size_t)b*8 + h)*NN + n] = a2;
            a3s[k] = a3;
        }
    }
    __syncthreads();

    float* Mb = g_M + (size_t)b*NN*8*NN;
    for (int i = 0; i < NN; i++) {
        float q[16];
        #pragma unroll
        for (int j = 0; j < 16; j += 4) {
            float4 v = *(const float4*)&sQe[i*128 + h*16 + j];
            q[j]=v.x; q[j+1]=v.y; q[j+2]=v.z; q[j+3]=v.w;
        }
        #pragma unroll
        for (int k = 0; k < 4; k++) {
            int n = lane + 32*k;
            if (n < NN) {
                float acc = 0.f;
                #pragma unroll
                for (int j = 0; j < 16; j++) acc += kr[k][j]*q[j];
                Mb[((size_t)i*8 + h)*NN + n] = acc + a3s[k];
            }
        }
    }
}

// ======================= decode kernel ======================================
// r11 arithmetic verbatim; B+C+G fused within-warp (warp h owns head h's
// softmax AND the glimpse columns d in [16h,16h+16), half = lane>>4).
// 3 syncthreads + 1 bar128 per step (was 4 + 2).
// smem: sK2 13200 + sAttn 832 + sG 128 + sU 128 + sMask 104 + sDem 104
//     = 14496 floats (58 KB) -> 3 CTAs/SM.
#define DEC_SMEM_FLOATS (NN*NPAD + 832 + 128 + 128 + 104 + 104)
#define DEC_SMEM (DEC_SMEM_FLOATS * 4)

__global__ __launch_bounds__(256, 3) void decode_kernel(const float* __restrict__ capacity,
                                                        const float* __restrict__ demand,
                                                        float* __restrict__ out)
{
    extern __shared__ float sm[];
    float* sK2   = sm;                    // [100][132]
    float* sAttn = sK2   + NN*NPAD;       // [8][104] halves at +0/+52 (unnormalized e)
    float* sG    = sAttn + 832;           // 128
    float* sU    = sG    + 128;           // 128 (pads 100..127 = -inf, never rewritten)
    float* sMask = sU    + 128;           // 104
    float* sDem  = sMask + 104;           // 104

    __shared__ float sCap;
    __shared__ int   sIdx;
    __shared__ int   sDone;

    int b = blockIdx.x, tid = threadIdx.x;
    int warp = tid >> 5, lane = tid & 31;
    // C/G mapping: warp h covers glimpse columns d = 16h + (lane&15), half = lane>>4
    int cd   = 16*warp + (lane & 15);
    int chalf= lane >> 4;

    // ---- loads ----
    {
        const float4* gK2 = (const float4*)(g_K2 + (size_t)b*NN*HH);
        for (int j = tid; j < NN*HH/4; j += 256) {
            int n = j >> 5; int c = (j & 31) << 2;
            *(float4*)&sK2[n*NPAD + c] = gK2[j];
        }
    }
    float vreg[50];
    {
        const float* vg = g_V + (size_t)b*NN*HH + (size_t)(chalf*50)*HH + cd;
        #pragma unroll
        for (int i = 0; i < 50; i++) vreg[i] = vg[i*HH];
    }
    if (tid < 100) sDem[tid] = demand[b*NN + tid];
    if (tid >= 100 && tid < 128) sU[tid] = -INFINITY;   // argmax pads (never rewritten)
    if (tid == 0) { sCap = capacity[b]; sIdx = 0; sDone = 0; }

    float c2reg[4];
    #pragma unroll
    for (int k = 0; k < 4; k++) {
        int n = lane + 32*k;
        c2reg[k] = (n < 100) ? g_C2[(size_t)b*800 + warp*100 + n] : 0.f;
    }
    float mrow[4];
    {
        const float* mp = g_M + ((size_t)b*NN*8 + warp)*NN;
        #pragma unroll
        for (int k = 0; k < 4; k++) { int n = lane + 32*k; mrow[k] = (n < NN) ? mp[n] : 0.f; }
    }
    __syncthreads();

    const float base_cap = capacity[0];

    // ---- initial mask (index=0, mask1=0, go_depot=1) ----
    if (warp == 0) {
        float cap0 = sCap; int cnt = 0;
        #pragma unroll
        for (int k = 0; k < 4; k++) {
            int n = lane + 32*k;
            if (n >= 1 && n < 100) {
                float m = (sDem[n] > cap0) ? 1.f : 0.f;
                sMask[n] = m;
                if (m == 0.f) cnt++;
            }
        }
        #pragma unroll
        for (int o = 16; o; o >>= 1) cnt += __shfl_xor_sync(0xffffffffu, cnt, o);
        if (lane == 0) sMask[0] = (cnt == 0) ? 0.f : 1.f;
    }
    __syncthreads();

    float logTot = 0.f;
    int   vis    = 0;
    unsigned m1bits = 0;   // warp0: mask1 bits for n = lane + 32k
    int sStop = STEPS;

    for (int s = 0; s < STEPS; s++) {
        // ==== B+C+G fused, entirely within warp h (head h) ====
        {
            // B: e = exp(score) unnormalized; warp-wide sum
            float cap = sCap;
            float e[4]; float sum = 0.f;
            #pragma unroll
            for (int k = 0; k < 4; k++) {
                int n = lane + 32*k;
                float ee = 0.f;
                if (n < 100) {
                    float v = (sMask[n] > 0.f) ? NEGV : fmaf(cap, c2reg[k], mrow[k]);
                    ee = __expf(v);
                }
                e[k] = ee; sum += ee;
            }
            #pragma unroll
            for (int o = 16; o; o >>= 1) sum += __shfl_xor_sync(0xffffffffu, sum, o);
            #pragma unroll
            for (int k = 0; k < 4; k++) {
                int n = lane + 32*k;
                if (n < 100) sAttn[warp*104 + n + ((n >= 50) ? 2 : 0)] = e[k];
            }
            float rden = 1.0f / sum;
            __syncwarp();

            // C: glimpse partial for (cd, chalf) — reads own warp's attn row
            const float* an = sAttn + warp*104 + chalf*52;
            float a0 = 0.f, a1 = 0.f, a2 = 0.f, a3 = 0.f;
            #pragma unroll
            for (int i = 0; i < 48; i += 4) {
                float4 a4 = *(const float4*)&an[i];
                a0 = fmaf(a4.x, vreg[i],   a0);
                a1 = fmaf(a4.y, vreg[i+1], a1);
                a2 = fmaf(a4.z, vreg[i+2], a2);
                a3 = fmaf(a4.w, vreg[i+3], a3);
            }
            a0 = fmaf(an[48], vreg[48], a0);
            a1 = fmaf(an[49], vreg[49], a1);
            float p = (a0 + a1) + (a2 + a3);

            // G: half-combine via shfl within warp; p0 + p1 order preserved
            float po = __shfl_xor_sync(0xffffffffu, p, 16);
            if (chalf == 0) sG[cd] = (p + po) * rden;
        }
        __syncthreads();   // sG complete (all 8 warps contributed)

        float uv[4]; float vmax = -INFINITY; int imax = 0;

        // ---- D (threads 0..99) + argmax (warp0) ----
        if (tid < 128) {
            if (tid < 100) {
                const float* kp = sK2 + tid*NPAD;
                float b0 = 0.f, b1 = 0.f, b2 = 0.f, b3 = 0.f;
                #pragma unroll
                for (int j = 0; j < 128; j += 16) {
                    float4 x, g;
                    x = *(const float4*)&kp[j];    g = *(const float4*)&sG[j];
                    b0 = fmaf(x.x,g.x,b0); b0 = fmaf(x.y,g.y,b0); b0 = fmaf(x.z,g.z,b0); b0 = fmaf(x.w,g.w,b0);
                    x = *(const float4*)&kp[j+4];  g = *(const float4*)&sG[j+4];
                    b1 = fmaf(x.x,g.x,b1); b1 = fmaf(x.y,g.y,b1); b1 = fmaf(x.z,g.z,b1); b1 = fmaf(x.w,g.w,b1);
                    x = *(const float4*)&kp[j+8];  g = *(const float4*)&sG[j+8];
                    b2 = fmaf(x.x,g.x,b2); b2 = fmaf(x.y,g.y,b2); b2 = fmaf(x.z,g.z,b2); b2 = fmaf(x.w,g.w,b2);
                    x = *(const float4*)&kp[j+12]; g = *(const float4*)&sG[j+12];
                    b3 = fmaf(x.x,g.x,b3); b3 = fmaf(x.y,g.y,b3); b3 = fmaf(x.z,g.z,b3); b3 = fmaf(x.w,g.w,b3);
                }
                float t = (b0 + b1) + (b2 + b3);
                sU[tid] = (sMask[tid] > 0.f) ? NEGV : 10.0f * tanhf(t);
            }
            asm volatile("bar.sync 1, 128;" ::: "memory");

            // warp0: argmax + publish sIdx ASAP (sU pads 100..127 are -inf)
            if (warp == 0) {
                #pragma unroll
                for (int k = 0; k < 4; k++) uv[k] = sU[lane + 32*k];
                #pragma unroll
                for (int k = 0; k < 4; k++) {
                    int n = lane + 32*k;
                    if (uv[k] > vmax) { vmax = uv[k]; imax = n; }
                }
                #pragma unroll
                for (int o = 16; o; o >>= 1) {
                    float ov = __shfl_down_sync(0xffffffffu, vmax, o);
                    int   oi = __shfl_down_sync(0xffffffffu, imax, o);
                    if (ov > vmax || (ov == vmax && oi < imax)) { vmax = ov; imax = oi; }
                }
                vmax = __shfl_sync(0xffffffffu, vmax, 0);
                imax = __shfl_sync(0xffffffffu, imax, 0);
                if (lane == 0) sIdx = imax;
            }
        }
        __syncthreads();   // publish sIdx

        // ---- ALL warps: prefetch next M row early (hides DRAM under tail) ----
        {
            int idx = sIdx;
            const float* mp = g_M + (((size_t)b*NN + idx)*8 + warp)*NN;
            #pragma unroll
            for (int k = 0; k < 4; k++) { int n = lane + 32*k; if (n < NN) mrow[k] = mp[n]; }
        }

        // ---- warp0 tail: logp, state, mask (overlaps M prefetch latency) ----
        if (warp == 0) {
            float sum = 0.f;
            #pragma unroll
            for (int k = 0; k < 4; k++) {
                int n = lane + 32*k;
                if (n < 100) sum += __expf(uv[k] - vmax);
            }
            #pragma unroll
            for (int o = 16; o; o >>= 1) sum += __shfl_xor_sync(0xffffffffu, sum, o);

            float capNew = 0.f;
            if (lane == 0) {
                float logp = -logf(sum);
                if (vis < 99) logTot += logp;
                out[(size_t)b*STEPS + s] = (float)imax;
                float seld = sDem[imax];
                capNew = (imax == 0) ? base_cap : (sCap - seld);
                sCap = capNew;
            }
            capNew = __shfl_sync(0xffffffffu, capNew, 0);

            // mask1 (bits) + vis
            int kbit = imax >> 5;
            int owner = (lane == (imax & 31));
            unsigned newly = (owner && imax > 0 && !((m1bits >> kbit) & 1u)) ? 1u : 0u;
            unsigned bal = __ballot_sync(0xffffffffu, newly);
            if (bal) vis += 1;
            if (owner && imax > 0) m1bits |= (1u << kbit);

            int goDepot = (imax == 0);
            int cnt = 0;
            #pragma unroll
            for (int k = 0; k < 4; k++) {
                int n = lane + 32*k;
                if (n >= 1 && n < 100) {
                    float m1v = ((m1bits >> k) & 1u) ? 1.f : 0.f;
                    float m = fmaxf(m1v, (sDem[n] > capNew) ? 1.f : 0.f);
                    sMask[n] = m;
                    if (m == 0.f) cnt++;
                }
            }
            #pragma unroll
            for (int o = 16; o; o >>= 1) cnt += __shfl_xor_sync(0xffffffffu, cnt, o);
            if (lane == 0) {
                sMask[0] = (cnt == 0) ? 0.f : (goDepot ? 1.f : 0.f);
                sDone = (vis == 99 && imax == 0) ? 1 : 0;   // absorbing state
            }
        }
        __syncthreads();

        if (sDone) { sStop = s + 1; break; }
    }

    // zero-fill remaining actions (absorbing state always selects depot; logp gated)
    for (int j = sStop + tid; j < STEPS; j += 256) out[(size_t)b*STEPS + j] = 0.f;
    if (tid == 0) out[(size_t)BB*STEPS + b] = logTot;
}

// ======================= launcher ===========================================
extern "C" void kernel_launch(void* const* d_in, const int* in_sizes, int n_in,
                              void* d_out, int out_size)
{
    const float* enc      = (const float*)d_in[0];
    const float* pool     = (const float*)d_in[1];
    const float* capacity = (const float*)d_in[2];
    const float* demand   = (const float*)d_in[3];
    const float* fc_w     = (const float*)d_in[4];
    const float* fc1_w    = (const float*)d_in[5];
    const float* Wq       = (const float*)d_in[6];
    const float* Wk       = (const float*)d_in[7];
    const float* Wv       = (const float*)d_in[8];
    const float* Wo       = (const float*)d_in[9];
    const float* Wk2      = (const float*)d_in[10];
    float* out = (float*)d_out;

    cudaFuncSetAttribute(gemm_kernel,      cudaFuncAttributeMaxDynamicSharedMemorySize, GEMM_SMEM);
    cudaFuncSetAttribute(score_pre_kernel, cudaFuncAttributeMaxDynamicSharedMemorySize, SP_SMEM);
    cudaFuncSetAttribute(decode_kernel,    cudaFuncAttributeMaxDynamicSharedMemorySize, DEC_SMEM);

    fold_kernel<<<dim3(128, 3), 132>>>(fc_w, fc1_w, Wq, Wo, Wk2);
    gemm_kernel<<<dim3((BB*NN)/GM_TILE, 5), 256, GEMM_SMEM>>>(enc, pool, Wk, Wv);
    score_pre_kernel<<<BB, 256, SP_SMEM>>>();
    decode_kernel<<<BB, 256, DEC_SMEM>>>(capacity, demand, out);
}

// round 14
// speedup vs baseline: 1.1299x; 1.0402x over previous
#include <cuda_runtime.h>
#include <math.h>

// Problem constants
#define BB   1024
#define NN   100
#define HH   128
#define STEPS 128
#define NEGV -1000000000.0f
#define NPAD 132

// packed f32x2 helpers (Blackwell FFMA2 — bit-identical per-lane IEEE fma)
#define PK2(d, x, y)  asm("mov.b64 %0, {%1, %2};" : "=l"(d) : "f"(x), "f"(y))
#define UPK2(x, y, d) asm("mov.b64 {%0, %1}, %2;" : "=f"(x), "=f"(y) : "l"(d))
#define FMA2(d, a, b) asm("fma.rn.f32x2 %0, %1, %2, %0;" : "+l"(d) : "l"(a), "l"(b))

// -------- device scratch ----
__device__ float g_K [BB*NN*HH];
__device__ float g_V [BB*NN*HH];
__device__ float g_K2[BB*NN*HH];
__device__ float g_Qe[BB*NN*HH];
__device__ float g_qpool[BB*HH];
__device__ float g_Wqf[HH*(HH+1)];
__device__ float g_WfoldT[HH*HH];
__device__ float g_Wpq[HH*HH];
__device__ float g_M [(size_t)BB*NN*8*NN];  // [b][i][h][n]  (C3 folded in)
__device__ float g_C2[BB*8*NN];             // [b][h][n]

// ======================= fold kernel =================================
__global__ void fold_kernel(const float* __restrict__ fc_w,
                            const float* __restrict__ fc1_w,
                            const float* __restrict__ Wq,
                            const float* __restrict__ Wo,
                            const float* __restrict__ Wk2)
{
    int mat = blockIdx.y;
    int r   = blockIdx.x;
    int j   = threadIdx.x;
    if (mat == 0) {
        if (j < 129) {
            float acc = 0.f;
            #pragma unroll 8
            for (int i = 0; i < 128; i++) acc += Wq[r*128 + i] * fc_w[i*129 + j];
            g_Wqf[r*129 + j] = 0.25f * acc;
        }
    } else if (mat == 1) {
        if (j < 128) {
            float acc = 0.f;
            #pragma unroll 8
            for (int i = 0; i < 128; i++) acc += Wk2[i*128 + j] * Wo[i*128 + r];
            g_WfoldT[r*128 + j] = (1.0f / sqrtf(128.0f)) * acc;
        }
    } else {
        if (j < 128) {
            float acc = 0.f;
            #pragma unroll 8
            for (int i = 0; i < 128; i++) acc += Wq[r*128 + i] * fc1_w[i*128 + j];
            g_Wpq[r*128 + j] = 0.25f * acc;
        }
    }
}

// ======================= GEMM: out = A @ W^T (FFMA2, A transposed in smem) ==
#define GM_TILE 64
#define ATPAD 68
#define GEMM_SMEM ((128*132 + 128*ATPAD) * 4)

__global__ __launch_bounds__(256) void gemm_kernel(const float* __restrict__ enc,
                                                   const float* __restrict__ pool,
                                                   const float* __restrict__ Wk,
                                                   const float* __restrict__ Wv)
{
    extern __shared__ float sm[];
    float* sW  = sm;                 // [128][132]  sW[k*132 + c] = W[c][k]
    float* sAT = sm + 128*132;       // [128][68]   sAT[k*68 + r] = A[row0+r][k]

    int slice = blockIdx.y;
    const float* A; const float* W; float* O; int rows; int ldw = 128;
    if      (slice == 0) { A = enc;  W = Wk;       O = g_K;     rows = BB*NN; }
    else if (slice == 1) { A = enc;  W = Wv;       O = g_V;     rows = BB*NN; }
    else if (slice == 2) { A = enc;  W = g_WfoldT; O = g_K2;    rows = BB*NN; }
    else if (slice == 3) { A = enc;  W = g_Wqf;    O = g_Qe;    rows = BB*NN; ldw = 129; }
    else                 { A = pool; W = g_Wpq;    O = g_qpool; rows = BB;    }

    int row0 = blockIdx.x * GM_TILE;
    if (row0 >= rows) return;
    int tid = threadIdx.x;

    for (int i = tid; i < 128*128; i += 256) {
        int c = i >> 7, m = i & 127;
        sW[m*132 + c] = W[c*ldw + m];
    }
    for (int i = tid; i < GM_TILE*128; i += 256) {
        int r = i >> 7, k = i & 127;
        sAT[k*ATPAD + r] = A[(row0 + r)*128 + k];
    }
    __syncthreads();

    int warp = tid >> 5, lane = tid & 31;
    int r0 = warp * 8, c0 = lane * 4;

    unsigned long long accp[4][4];
    #pragma unroll
    for (int c = 0; c < 4; c++)
        #pragma unroll
        for (int t = 0; t < 4; t++) PK2(accp[c][t], 0.f, 0.f);

    #pragma unroll 4
    for (int k = 0; k < 128; k++) {
        float4 w4 = *(const float4*)&sW[k*132 + c0];
        unsigned long long wd[4];
        PK2(wd[0], w4.x, w4.x); PK2(wd[1], w4.y, w4.y);
        PK2(wd[2], w4.z, w4.z); PK2(wd[3], w4.w, w4.w);
        float4 a04 = *(const float4*)&sAT[k*ATPAD + r0];
        float4 a14 = *(const float4*)&sAT[k*ATPAD + r0 + 4];
        unsigned long long ap[4];
        PK2(ap[0], a04.x, a04.y);
        PK2(ap[1], a04.z, a04.w);
        PK2(ap[2], a14.x, a14.y);
        PK2(ap[3], a14.z, a14.w);
        #pragma unroll
        for (int c = 0; c < 4; c++)
            #pragma unroll
            for (int t = 0; t < 4; t++) FMA2(accp[c][t], ap[t], wd[c]);
    }

    #pragma unroll
    for (int t = 0; t < 4; t++) {
        float4 v0, v1;
        UPK2(v0.x, v1.x, accp[0][t]);
        UPK2(v0.y, v1.y, accp[1][t]);
        UPK2(v0.z, v1.z, accp[2][t]);
        UPK2(v0.w, v1.w, accp[3][t]);
        *(float4*)&O[(size_t)(row0 + r0 + 2*t    )*128 + c0] = v0;
        *(float4*)&O[(size_t)(row0 + r0 + 2*t + 1)*128 + c0] = v1;
    }
}

// ======================= score precompute (FFMA2 over k-group pairs) ========
// M'[b,i,h,n] = dot16(Qe[i,h],K[n,h]) + a3s[n];  C2 = dot16(K,Wc)
// Dots keep exact scalar fma chain order per element -> M bit-identical.
#define SP_SMEM (NN*128*4)
__global__ __launch_bounds__(256, 2) void score_pre_kernel()
{
    extern __shared__ float sQe[];
    int b = blockIdx.x, tid = threadIdx.x;
    int h = tid >> 5, lane = tid & 31;

    const float* qe = g_Qe + (size_t)b*NN*HH;
    for (int j = tid; j < NN*HH/4; j += 256)
        *(float4*)&sQe[j*4] = ((const float4*)qe)[j];

    float kr[4][16];
    float wc[16], qp[16];
    #pragma unroll
    for (int j = 0; j < 16; j++) {
        wc[j] = g_Wqf[(h*16+j)*129 + 128];
        qp[j] = g_qpool[b*HH + h*16 + j];
    }
    #pragma unroll
    for (int k = 0; k < 4; k++) {
        int n = lane + 32*k;
        if (n < NN) {
            const float* kp = g_K + (size_t)b*NN*HH + (size_t)n*HH + h*16;
            #pragma unroll
            for (int j = 0; j < 16; j += 4) {
                float4 v = *(const float4*)&kp[j];
                kr[k][j]=v.x; kr[k][j+1]=v.y; kr[k][j+2]=v.z; kr[k][j+3]=v.w;
            }
        } else {
            #pragma unroll
            for (int j = 0; j < 16; j++) kr[k][j] = 0.f;
        }
    }
    float a3s[4];
    #pragma unroll
    for (int k = 0; k < 4; k++) {
        int n = lane + 32*k;
        a3s[k] = 0.f;
        if (n < NN) {
            float a2 = 0.f, a3 = 0.f;
            #pragma unroll
            for (int j = 0; j < 16; j++) { a2 += kr[k][j]*wc[j]; a3 += kr[k][j]*qp[j]; }
            g_C2[((size_t)b*8 + h)*NN + n] = a2;
            a3s[k] = a3;
        }
    }
    __syncthreads();

    // pack kr pairs (k0,k1) and (k2,k3) once — hoisted out of i-loop
    unsigned long long krp[2][16];
    #pragma unroll
    for (int m = 0; m < 2; m++)
        #pragma unroll
        for (int j = 0; j < 16; j++) PK2(krp[m][j], kr[2*m][j], kr[2*m+1][j]);

    float* Mb = g_M + (size_t)b*NN*8*NN;
    for (int i = 0; i < NN; i++) {
        unsigned long long qpk[16];
        #pragma unroll
        for (int j = 0; j < 16; j += 4) {
            float4 v = *(const float4*)&sQe[i*128 + h*16 + j];
            PK2(qpk[j  ], v.x, v.x);
            PK2(qpk[j+1], v.y, v.y);
            PK2(qpk[j+2], v.z, v.z);
            PK2(qpk[j+3], v.w, v.w);
        }
        float* Mrow = Mb + ((size_t)i*8 + h)*NN;
        #pragma unroll
        for (int m = 0; m < 2; m++) {
            unsigned long long acc;
            PK2(acc, 0.f, 0.f);
            #pragma unroll
            for (int j = 0; j < 16; j++) FMA2(acc, krp[m][j], qpk[j]);
            float d0, d1;
            UPK2(d0, d1, acc);
            int n0 = lane + 32*(2*m);       // k = 0 or 2 -> always < 100
            int n1 = lane + 32*(2*m + 1);   // k = 1 or 3 -> guard k=3
            Mrow[n0] = d0 + a3s[2*m];
            if (n1 < NN) Mrow[n1] = d1 + a3s[2*m + 1];
        }
    }
}

// ======================= decode kernel ======================================
// EXACT r11 decode (best measured: 993us / 1458 total). Do not touch.
// smem ~59 KB -> 3 CTAs/SM.
#define DEC_SMEM_FLOATS (NN*NPAD + 832 + 8 + 256 + 128 + 128 + 104 + 104)
#define DEC_SMEM (DEC_SMEM_FLOATS * 4)

__global__ __launch_bounds__(256, 3) void decode_kernel(const float* __restrict__ capacity,
                                                        const float* __restrict__ demand,
                                                        float* __restrict__ out)
{
    extern __shared__ float sm[];
    float* sK2   = sm;                    // [100][132]
    float* sAttn = sK2   + NN*NPAD;       // [8][104] halves at +0/+52 (unnormalized e)
    float* sRden = sAttn + 832;           // 8
    float* sPartA= sRden + 8;             // 256
    float* sG    = sPartA+ 256;           // 128
    float* sU    = sG    + 128;           // 128 (pads 100..127 = -inf, never rewritten)
    float* sMask = sU    + 128;           // 104
    float* sDem  = sMask + 104;           // 104

    __shared__ float sCap;
    __shared__ int   sIdx;
    __shared__ int   sDone;

    int b = blockIdx.x, tid = threadIdx.x;
    int warp = tid >> 5, lane = tid & 31;
    int d = tid & 127, half = tid >> 7, hh = d >> 4;

    // ---- loads ----
    {
        const float4* gK2 = (const float4*)(g_K2 + (size_t)b*NN*HH);
        for (int j = tid; j < NN*HH/4; j += 256) {
            int n = j >> 5; int c = (j & 31) << 2;
            *(float4*)&sK2[n*NPAD + c] = gK2[j];
        }
    }
    float vreg[50];
    {
        const float* vg = g_V + (size_t)b*NN*HH + (size_t)(half*50)*HH + d;
        #pragma unroll
        for (int i = 0; i < 50; i++) vreg[i] = vg[i*HH];
    }
    if (tid < 100) sDem[tid] = demand[b*NN + tid];
    if (tid >= 100 && tid < 128) sU[tid] = -INFINITY;   // argmax pads (never rewritten)
    if (tid == 0) { sCap = capacity[b]; sIdx = 0; sDone = 0; }

    float c2reg[4];
    #pragma unroll
    for (int k = 0; k < 4; k++) {
        int n = lane + 32*k;
        c2reg[k] = (n < 100) ? g_C2[(size_t)b*800 + warp*100 + n] : 0.f;
    }
    float mrow[4];
    {
        const float* mp = g_M + ((size_t)b*NN*8 + warp)*NN;
        #pragma unroll
        for (int k = 0; k < 4; k++) { int n = lane + 32*k; mrow[k] = (n < NN) ? mp[n] : 0.f; }
    }
    __syncthreads();

    const float base_cap = capacity[0];

    // ---- initial mask (index=0, mask1=0, go_depot=1) ----
    if (warp == 0) {
        float cap0 = sCap; int cnt = 0;
        #pragma unroll
        for (int k = 0; k < 4; k++) {
            int n = lane + 32*k;
            if (n >= 1 && n < 100) {
                float m = (sDem[n] > cap0) ? 1.f : 0.f;
                sMask[n] = m;
                if (m == 0.f) cnt++;
            }
        }
        #pragma unroll
        for (int o = 16; o; o >>= 1) cnt += __shfl_xor_sync(0xffffffffu, cnt, o);
        if (lane == 0) sMask[0] = (cnt == 0) ? 0.f : 1.f;
    }
    __syncthreads();

    float logTot = 0.f;
    int   vis    = 0;
    unsigned m1bits = 0;   // warp0: mask1 bits for n = lane + 32k
    int sStop = STEPS;

    for (int s = 0; s < STEPS; s++) {
        // ---- B: e = exp(score) unnormalized; per-head 1/sum ----
        {
            float cap = sCap;
            float e[4]; float sum = 0.f;
            #pragma unroll
            for (int k = 0; k < 4; k++) {
                int n = lane + 32*k;
                float ee = 0.f;
                if (n < 100) {
                    float v = (sMask[n] > 0.f) ? NEGV : fmaf(cap, c2reg[k], mrow[k]);
                    ee = __expf(v);
                }
                e[k] = ee; sum += ee;
            }
            #pragma unroll
            for (int o = 16; o; o >>= 1) sum += __shfl_xor_sync(0xffffffffu, sum, o);
            #pragma unroll
            for (int k = 0; k < 4; k++) {
                int n = lane + 32*k;
                if (n < 100) sAttn[warp*104 + n + ((n >= 50) ? 2 : 0)] = e[k];
            }
            if (lane == 0) sRden[warp] = 1.0f / sum;
        }
        __syncthreads();

        // ---- C: glimpse partials (V in regs, 4 accumulators) ----
        {
            const float* an = sAttn + hh*104 + half*52;
            float a0 = 0.f, a1 = 0.f, a2 = 0.f, a3 = 0.f;
            #pragma unroll
            for (int i = 0; i < 48; i += 4) {
                float4 a4 = *(const float4*)&an[i];
                a0 = fmaf(a4.x, vreg[i],   a0);
                a1 = fmaf(a4.y, vreg[i+1], a1);
                a2 = fmaf(a4.z, vreg[i+2], a2);
                a3 = fmaf(a4.w, vreg[i+3], a3);
            }
            a0 = fmaf(an[48], vreg[48], a0);
            a1 = fmaf(an[49], vreg[49], a1);
            sPartA[tid] = (a0 + a1) + (a2 + a3);
        }
        __syncthreads();

        float uv[4]; float vmax = -INFINITY; int imax = 0;

        // ---- warps 0-3: g-combine (deferred 1/sum), u, argmax ----
        if (tid < 128) {
            sG[tid] = (sPartA[tid] + sPartA[tid + 128]) * sRden[hh];
            asm volatile("bar.sync 1, 128;" ::: "memory");

            if (tid < 100) {
                const float* kp = sK2 + tid*NPAD;
                float b0 = 0.f, b1 = 0.f, b2 = 0.f, b3 = 0.f;
                #pragma unroll
                for (int j = 0; j < 128; j += 16) {
                    float4 x, g;
                    x = *(const float4*)&kp[j];    g = *(const float4*)&sG[j];
                    b0 = fmaf(x.x,g.x,b0); b0 = fmaf(x.y,g.y,b0); b0 = fmaf(x.z,g.z,b0); b0 = fmaf(x.w,g.w,b0);
                    x = *(const float4*)&kp[j+4];  g = *(const float4*)&sG[j+4];
                    b1 = fmaf(x.x,g.x,b1); b1 = fmaf(x.y,g.y,b1); b1 = fmaf(x.z,g.z,b1); b1 = fmaf(x.w,g.w,b1);
                    x = *(const float4*)&kp[j+8];  g = *(const float4*)&sG[j+8];
                    b2 = fmaf(x.x,g.x,b2); b2 = fmaf(x.y,g.y,b2); b2 = fmaf(x.z,g.z,b2); b2 = fmaf(x.w,g.w,b2);
                    x = *(const float4*)&kp[j+12]; g = *(const float4*)&sG[j+12];
                    b3 = fmaf(x.x,g.x,b3); b3 = fmaf(x.y,g.y,b3); b3 = fmaf(x.z,g.z,b3); b3 = fmaf(x.w,g.w,b3);
                }
                float t = (b0 + b1) + (b2 + b3);
                sU[tid] = (sMask[tid] > 0.f) ? NEGV : 10.0f * tanhf(t);
            }
            asm volatile("bar.sync 1, 128;" ::: "memory");

            // warp0: argmax + publish sIdx ASAP (sU pads 100..127 are -inf)
            if (warp == 0) {
                #pragma unroll
                for (int k = 0; k < 4; k++) uv[k] = sU[lane + 32*k];
                #pragma unroll
                for (int k = 0; k < 4; k++) {
                    int n = lane + 32*k;
                    if (uv[k] > vmax) { vmax = uv[k]; imax = n; }
                }
                #pragma unroll
                for (int o = 16; o; o >>= 1) {
                    float ov = __shfl_down_sync(0xffffffffu, vmax, o);
                    int   oi = __shfl_down_sync(0xffffffffu, imax, o);
                    if (ov > vmax || (ov == vmax && oi < imax)) { vmax = ov; imax = oi; }
                }
                vmax = __shfl_sync(0xffffffffu, vmax, 0);
                imax = __shfl_sync(0xffffffffu, imax, 0);
                if (lane == 0) sIdx = imax;
            }
        }
        __syncthreads();   // publish sIdx

        // ---- ALL warps: prefetch next M row early (hides DRAM under tail) ----
        {
            int idx = sIdx;
            const float* mp = g_M + (((size_t)b*NN + idx)*8 + warp)*NN;
            #pragma unroll
            for (int k = 0; k < 4; k++) { int n = lane + 32*k; if (n < NN) mrow[k] = mp[n]; }
        }

        // ---- warp0 tail: logp, state, mask (overlaps M prefetch latency) ----
        if (warp == 0) {
            float sum = 0.f;
            #pragma unroll
            for (int k = 0; k < 4; k++) {
                int n = lane + 32*k;
                if (n < 100) sum += __expf(uv[k] - vmax);
            }
            #pragma unroll
            for (int o = 16; o; o >>= 1) sum += __shfl_xor_sync(0xffffffffu, sum, o);

            float capNew = 0.f;
            if (lane == 0) {
                float logp = -logf(sum);
                if (vis < 99) logTot += logp;
                out[(size_t)b*STEPS + s] = (float)imax;
                float seld = sDem[imax];
                capNew = (imax == 0) ? base_cap : (sCap - seld);
                sCap = capNew;
            }
            capNew = __shfl_sync(0xffffffffu, capNew, 0);

            // mask1 (bits) + vis
            int kbit = imax >> 5;
            int owner = (lane == (imax & 31));
            unsigned newly = (owner && imax > 0 && !((m1bits >> kbit) & 1u)) ? 1u : 0u;
            unsigned bal = __ballot_sync(0xffffffffu, newly);
            if (bal) vis += 1;
            if (owner && imax > 0) m1bits |= (1u << kbit);

            int goDepot = (imax == 0);
            int cnt = 0;
            #pragma unroll
            for (int k = 0; k < 4; k++) {
                int n = lane + 32*k;
                if (n >= 1 && n < 100) {
                    float m1v = ((m1bits >> k) & 1u) ? 1.f : 0.f;
                    float m = fmaxf(m1v, (sDem[n] > capNew) ? 1.f : 0.f);
                    sMask[n] = m;
                    if (m == 0.f) cnt++;
                }
            }
            #pragma unroll
            for (int o = 16; o; o >>= 1) cnt += __shfl_xor_sync(0xffffffffu, cnt, o);
            if (lane == 0) {
                sMask[0] = (cnt == 0) ? 0.f : (goDepot ? 1.f : 0.f);
                sDone = (vis == 99 && imax == 0) ? 1 : 0;   // absorbing state
            }
        }
        __syncthreads();

        if (sDone) { sStop = s + 1; break; }
    }

    // zero-fill remaining actions (absorbing state always selects depot; logp gated)
    for (int j = sStop + tid; j < STEPS; j += 256) out[(size_t)b*STEPS + j] = 0.f;
    if (tid == 0) out[(size_t)BB*STEPS + b] = logTot;
}

// ======================= launcher ===========================================
extern "C" void kernel_launch(void* const* d_in, const int* in_sizes, int n_in,
                              void* d_out, int out_size)
{
    const float* enc      = (const float*)d_in[0];
    const float* pool     = (const float*)d_in[1];
    const float* capacity = (const float*)d_in[2];
    const float* demand   = (const float*)d_in[3];
    const float* fc_w     = (const float*)d_in[4];
    const float* fc1_w    = (const float*)d_in[5];
    const float* Wq       = (const float*)d_in[6];
    const float* Wk       = (const float*)d_in[7];
    const float* Wv       = (const float*)d_in[8];
    const float* Wo       = (const float*)d_in[9];
    const float* Wk2      = (const float*)d_in[10];
    float* out = (float*)d_out;

    cudaFuncSetAttribute(gemm_kernel,      cudaFuncAttributeMaxDynamicSharedMemorySize, GEMM_SMEM);
    cudaFuncSetAttribute(score_pre_kernel, cudaFuncAttributeMaxDynamicSharedMemorySize, SP_SMEM);
    cudaFuncSetAttribute(decode_kernel,    cudaFuncAttributeMaxDynamicSharedMemorySize, DEC_SMEM);

    fold_kernel<<<dim3(128, 3), 132>>>(fc_w, fc1_w, Wq, Wo, Wk2);
    gemm_kernel<<<dim3((BB*NN)/GM_TILE, 5), 256, GEMM_SMEM>>>(enc, pool, Wk, Wv);
    score_pre_kernel<<<BB, 256, SP_SMEM>>>();
    decode_kernel<<<BB, 256, DEC_SMEM>>>(capacity, demand, out);
}